// round 2
// baseline (speedup 1.0000x reference)
#include <cuda_runtime.h>
#include <math.h>

// Problem constants
#define BATCH 4096
#define DIN   1024
#define DOUT  1024
#define D2    2048   // 2*OUT
#define D3    3072   // 3*OUT

// GEMM tiling
#define BM 128
#define BN 128
#define BK 16
#define TM 8
#define TN 8
#define NTHREADS 256

// Scratch (allocation-free requirement -> __device__ globals)
__device__ float g_act[(size_t)BATCH * D2];   // activated [B, 2*OUT]
__device__ float g_z[(size_t)BATCH * DOUT];   // z gate    [B, OUT]
__device__ float g_rh[(size_t)BATCH * DOUT];  // r*h_prev  [B, OUT]

struct SmemT {
    float As[BK][BM];
    float Bs[BK][BN];
};

// Segmented-K GEMM core: A is logically [M, Ktot] = [A0 (cols 0..K0) | A1 (cols K0..Ktot)],
// both row-major with their own leading dims. B is row-major [Ktot, ldb], starting col n0.
// Computes acc += A[m0:m0+128, :] @ B[:, n0:n0+128] for this block's 128x128 tile.
__device__ __forceinline__ void gemm_core(
    const float* __restrict__ A0, int lda0,
    const float* __restrict__ A1, int lda1, int K0,
    const float* __restrict__ B, int ldb, int Ktot,
    int m0, int n0, float acc[TM][TN], SmemT& s)
{
    const int tid = threadIdx.x;
    const int tx = tid & 15;        // 0..15 (n direction)
    const int ty = tid >> 4;        // 0..15 (m direction)

    for (int kt = 0; kt < Ktot; kt += BK) {
        const float* Aseg;
        int lda;
        if (kt < K0) { Aseg = A0 + kt;        lda = lda0; }
        else         { Aseg = A1 + (kt - K0); lda = lda1; }

        // Load A tile (BM x BK), store transposed As[k][m]
        #pragma unroll
        for (int i = 0; i < 2; i++) {
            int idx = tid + i * NTHREADS;          // 0..511
            int row = idx >> 2;                    // 0..127
            int kc  = (idx & 3) * 4;               // 0,4,8,12
            float4 v = *(const float4*)(Aseg + (size_t)(m0 + row) * lda + kc);
            s.As[kc + 0][row] = v.x;
            s.As[kc + 1][row] = v.y;
            s.As[kc + 2][row] = v.z;
            s.As[kc + 3][row] = v.w;
        }
        // Load B tile (BK x BN)
        #pragma unroll
        for (int i = 0; i < 2; i++) {
            int idx = tid + i * NTHREADS;          // 0..511
            int row = idx >> 5;                    // 0..15
            int c   = (idx & 31) * 4;              // 0..124
            *(float4*)&s.Bs[row][c] =
                *(const float4*)(B + (size_t)(kt + row) * ldb + n0 + c);
        }
        __syncthreads();

        #pragma unroll
        for (int k = 0; k < BK; k++) {
            float a[TM], b[TN];
            *(float4*)&a[0] = *(const float4*)&s.As[k][ty * TM];
            *(float4*)&a[4] = *(const float4*)&s.As[k][ty * TM + 4];
            *(float4*)&b[0] = *(const float4*)&s.Bs[k][tx * TN];
            *(float4*)&b[4] = *(const float4*)&s.Bs[k][tx * TN + 4];
            #pragma unroll
            for (int i = 0; i < TM; i++)
                #pragma unroll
                for (int j = 0; j < TN; j++)
                    acc[i][j] = fmaf(a[i], b[j], acc[i][j]);
        }
        __syncthreads();
    }
}

// ---------------------------------------------------------------------------
// Kernel 1: new_x = [x, h_prev] @ W_in + b_in; spike logic; writes g_act and
// pot_next (into d_out's pot section).
// ---------------------------------------------------------------------------
__global__ __launch_bounds__(NTHREADS)
void k1_input_gemm(const float* __restrict__ x,
                   const float* __restrict__ h_prev,
                   const float* __restrict__ pot_prev,
                   const float* __restrict__ W_in,
                   const float* __restrict__ b_in,
                   const float* __restrict__ tresh,
                   const float* __restrict__ decay,
                   float* __restrict__ pot_out)
{
    __shared__ SmemT s;
    float acc[TM][TN];
    #pragma unroll
    for (int i = 0; i < TM; i++)
        #pragma unroll
        for (int j = 0; j < TN; j++) acc[i][j] = 0.f;

    const int m0 = blockIdx.y * BM;
    const int n0 = blockIdx.x * BN;

    gemm_core(x, DIN, h_prev, DOUT, DIN, W_in, D2, DIN + DOUT, m0, n0, acc, s);

    const int tx = threadIdx.x & 15;
    const int ty = threadIdx.x >> 4;

    float bin[TN], th[TN], dc[TN];
    #pragma unroll
    for (int j = 0; j < TN; j++) {
        int n = n0 + tx * TN + j;
        bin[j] = b_in[n];
        th[j]  = tresh[n];
        dc[j]  = decay[n];
    }

    #pragma unroll
    for (int i = 0; i < TM; i++) {
        int m = m0 + ty * TM + i;
        size_t base = (size_t)m * D2 + n0 + tx * TN;
        float av[TN], pv[TN];
        #pragma unroll
        for (int j = 0; j < TN; j++) {
            float pt = pot_prev[base + j] + acc[i][j] + bin[j];
            bool spiked = pt > th[j];
            av[j] = spiked ? pt : 0.f;
            pv[j] = spiked ? 0.f : pt * dc[j];
        }
        #pragma unroll
        for (int j = 0; j < TN; j += 4) {
            *(float4*)&g_act[base + j]  = *(float4*)&av[j];
            *(float4*)&pot_out[base + j] = *(float4*)&pv[j];
        }
    }
}

// ---------------------------------------------------------------------------
// Kernel 2: z and r gates. Logical N = 2048 (first 1024 -> z, second -> r).
// A = [g_act, h_prev] (K = 3072). z stored to g_z; r combined as g_rh = h*r.
// ---------------------------------------------------------------------------
__global__ __launch_bounds__(NTHREADS)
void k2_zr_gemm(const float* __restrict__ h_prev,
                const float* __restrict__ W_z,
                const float* __restrict__ b_z,
                const float* __restrict__ W_r,
                const float* __restrict__ b_r)
{
    __shared__ SmemT s;
    float acc[TM][TN];
    #pragma unroll
    for (int i = 0; i < TM; i++)
        #pragma unroll
        for (int j = 0; j < TN; j++) acc[i][j] = 0.f;

    const int m0 = blockIdx.y * BM;
    const int n0g = blockIdx.x * BN;      // global 0..2047
    const bool isZ = (n0g < DOUT);
    const int n0 = isZ ? n0g : (n0g - DOUT);
    const float* W  = isZ ? W_z : W_r;
    const float* bs = isZ ? b_z : b_r;

    gemm_core(g_act, D2, h_prev, DOUT, D2, W, DOUT, D3, m0, n0, acc, s);

    const int tx = threadIdx.x & 15;
    const int ty = threadIdx.x >> 4;

    float bb[TN];
    #pragma unroll
    for (int j = 0; j < TN; j++) bb[j] = bs[n0 + tx * TN + j];

    #pragma unroll
    for (int i = 0; i < TM; i++) {
        int m = m0 + ty * TM + i;
        size_t base = (size_t)m * DOUT + n0 + tx * TN;
        float out[TN];
        #pragma unroll
        for (int j = 0; j < TN; j++) {
            float sg = 1.f / (1.f + expf(-(acc[i][j] + bb[j])));
            out[j] = isZ ? sg : sg * h_prev[base + j];
        }
        float* dst = isZ ? g_z : g_rh;
        #pragma unroll
        for (int j = 0; j < TN; j += 4)
            *(float4*)&dst[base + j] = *(float4*)&out[j];
    }
}

// ---------------------------------------------------------------------------
// Kernel 3: n = tanh([g_act, g_rh] @ W_n + b_n); h_next = (1-z)*h + z*n.
// ---------------------------------------------------------------------------
__global__ __launch_bounds__(NTHREADS)
void k3_cand_gemm(const float* __restrict__ h_prev,
                  const float* __restrict__ W_n,
                  const float* __restrict__ b_n,
                  float* __restrict__ h_out)
{
    __shared__ SmemT s;
    float acc[TM][TN];
    #pragma unroll
    for (int i = 0; i < TM; i++)
        #pragma unroll
        for (int j = 0; j < TN; j++) acc[i][j] = 0.f;

    const int m0 = blockIdx.y * BM;
    const int n0 = blockIdx.x * BN;

    gemm_core(g_act, D2, g_rh, DOUT, D2, W_n, DOUT, D3, m0, n0, acc, s);

    const int tx = threadIdx.x & 15;
    const int ty = threadIdx.x >> 4;

    float bb[TN];
    #pragma unroll
    for (int j = 0; j < TN; j++) bb[j] = b_n[n0 + tx * TN + j];

    #pragma unroll
    for (int i = 0; i < TM; i++) {
        int m = m0 + ty * TM + i;
        size_t base = (size_t)m * DOUT + n0 + tx * TN;
        float out[TN];
        #pragma unroll
        for (int j = 0; j < TN; j++) {
            float nv = tanhf(acc[i][j] + bb[j]);
            float z  = g_z[base + j];
            out[j] = (1.f - z) * h_prev[base + j] + z * nv;
        }
        #pragma unroll
        for (int j = 0; j < TN; j += 4)
            *(float4*)&h_out[base + j] = *(float4*)&out[j];
    }
}

// ---------------------------------------------------------------------------
// Launch
// ---------------------------------------------------------------------------
extern "C" void kernel_launch(void* const* d_in, const int* in_sizes, int n_in,
                              void* d_out, int out_size)
{
    const float* x        = (const float*)d_in[0];
    const float* h_prev   = (const float*)d_in[1];
    const float* pot_prev = (const float*)d_in[2];
    const float* W_in     = (const float*)d_in[3];
    const float* b_in     = (const float*)d_in[4];
    const float* tresh    = (const float*)d_in[5];
    const float* decay    = (const float*)d_in[6];
    const float* W_z      = (const float*)d_in[7];
    const float* b_z      = (const float*)d_in[8];
    const float* W_r      = (const float*)d_in[9];
    const float* b_r      = (const float*)d_in[10];
    const float* W_n      = (const float*)d_in[11];
    const float* b_n      = (const float*)d_in[12];

    float* h_out   = (float*)d_out;                          // [B, OUT]
    float* pot_out = (float*)d_out + (size_t)BATCH * DOUT;   // [B, 2*OUT]

    dim3 block(NTHREADS);
    dim3 grid1(D2 / BN, BATCH / BM);    // 16 x 32
    dim3 grid2(D2 / BN, BATCH / BM);    // 16 x 32 (z | r)
    dim3 grid3(DOUT / BN, BATCH / BM);  // 8 x 32

    k1_input_gemm<<<grid1, block>>>(x, h_prev, pot_prev, W_in, b_in, tresh, decay, pot_out);
    k2_zr_gemm<<<grid2, block>>>(h_prev, W_z, b_z, W_r, b_r);
    k3_cand_gemm<<<grid3, block>>>(h_prev, W_n, b_n, h_out);
}